// round 8
// baseline (speedup 1.0000x reference)
#include <cuda_runtime.h>
#include <cuda_bf16.h>
#include <cstdint>
#include <cstddef>

#define NTOK 65536  // 16 * 64 * 64 tokens

// ---------------- scratch (no allocations allowed) ----------------
__device__ __nv_bfloat16 g_xn_h [(size_t)NTOK * 256];
__device__ __nv_bfloat16 g_xn_l [(size_t)NTOK * 256];
__device__ float         g_qkv  [(size_t)NTOK * 768];
__device__ __nv_bfloat16 g_at_h [(size_t)NTOK * 256];
__device__ __nv_bfloat16 g_at_l [(size_t)NTOK * 256];
__device__ __nv_bfloat16 g_tmp_h[(size_t)NTOK * 256];
__device__ __nv_bfloat16 g_tmp_l[(size_t)NTOK * 256];
__device__ float         g_attn2[(size_t)NTOK * 256];
__device__ float         g_y    [(size_t)NTOK * 256];
__device__ __nv_bfloat16 g_z_h  [(size_t)NTOK * 256];
__device__ __nv_bfloat16 g_z_l  [(size_t)NTOK * 256];
__device__ __nv_bfloat16 g_h1_h [(size_t)NTOK * 1024];
__device__ __nv_bfloat16 g_h1_l [(size_t)NTOK * 1024];
__device__ float         g_mlp  [(size_t)NTOK * 256];
// packed bf16 hi/lo weights: in_w(196608) out_w(65536) proj_w(65536) fc1_w(262144) fc2_w(262144)
__device__ __nv_bfloat16 g_w_h[851968];
__device__ __nv_bfloat16 g_w_l[851968];

#define OFF_INW  0
#define OFF_OUTW 196608
#define OFF_PRJW 262144
#define OFF_FC1W 327680
#define OFF_FC2W 589824

// ---------------- small helpers ----------------
__device__ __forceinline__ void split2(float v, __nv_bfloat16& h, __nv_bfloat16& l) {
    h = __float2bfloat16(v);
    l = __float2bfloat16(v - __bfloat162float(h));
}

__device__ __forceinline__ uint32_t smem_u32(const void* p) {
    uint32_t a;
    asm("{ .reg .u64 t; cvta.to.shared.u64 t, %1; cvt.u32.u64 %0, t; }" : "=r"(a) : "l"(p));
    return a;
}

#define CPA16(dst, src) \
    asm volatile("cp.async.cg.shared.global [%0], [%1], 16;\n" :: "r"(dst), "l"(src))
#define CPA_COMMIT() asm volatile("cp.async.commit_group;\n" ::: "memory")
#define CPA_WAIT1()  asm volatile("cp.async.wait_group 1;\n" ::: "memory")
#define CPA_WAIT0()  asm volatile("cp.async.wait_group 0;\n" ::: "memory")

__device__ __forceinline__ void ldsm4(uint32_t* r, uint32_t addr) {
    asm volatile("ldmatrix.sync.aligned.m8n8.x4.shared.b16 {%0,%1,%2,%3}, [%4];\n"
                 : "=r"(r[0]), "=r"(r[1]), "=r"(r[2]), "=r"(r[3]) : "r"(addr));
}
__device__ __forceinline__ void mma16816(float* c, const uint32_t* a, uint32_t b0, uint32_t b1) {
    asm volatile(
        "mma.sync.aligned.m16n8k16.row.col.f32.bf16.bf16.f32 "
        "{%0,%1,%2,%3}, {%4,%5,%6,%7}, {%8,%9}, {%0,%1,%2,%3};\n"
        : "+f"(c[0]), "+f"(c[1]), "+f"(c[2]), "+f"(c[3])
        : "r"(a[0]), "r"(a[1]), "r"(a[2]), "r"(a[3]), "r"(b0), "r"(b1));
}

// ---------------- mma.sync split-bf16 GEMM ----------------
// C[M,N] = A[M,K] @ B[N,K]^T + bias, A/B as (hi,lo) bf16 pairs; 3-pass split.
// Block 128x128, 8 warps (2x4), warp tile 64x32, BK=32.
// 3-stage cp.async pipeline, ONE __syncthreads per chunk, hoisted fragments.
// smem tile: 128 rows x 80B (64B data + 16B pad) -> ldmatrix conflict-free.
#define ROW_B       80
#define TILE_B      (128 * ROW_B)     // 10240
#define STAGE_B     (4 * TILE_B)      // Ah | Al | Bh | Bl = 40960
#define GEMM_SMEM   (3 * STAGE_B)     // 122880

template <int OUTMODE /*0=f32, 1=hilo*/, bool GELU>
__global__ __launch_bounds__(256)
void mma_gemm(const __nv_bfloat16* __restrict__ Ah, const __nv_bfloat16* __restrict__ Al,
              const __nv_bfloat16* __restrict__ Bh, const __nv_bfloat16* __restrict__ Bl,
              const float* __restrict__ bias,
              float* __restrict__ Cf,
              __nv_bfloat16* __restrict__ Ch, __nv_bfloat16* __restrict__ Cl,
              int N, int K) {
    extern __shared__ char smem[];
    const uint32_t sb0 = smem_u32(smem);
    const int tid = threadIdx.x, lane = tid & 31, wid = tid >> 5;
    const int wm = wid >> 2, wn = wid & 3;        // 2 x 4 warp grid
    const int bm = blockIdx.y * 128, bn = blockIdx.x * 128;

    float acc[4][4][4];
#pragma unroll
    for (int i = 0; i < 4; i++)
#pragma unroll
        for (int j = 0; j < 4; j++)
#pragma unroll
            for (int k = 0; k < 4; k++) acc[i][j][k] = 0.f;

    const int nc = K >> 5;  // BK=32 chunks

    auto load_stage = [&](int c, int s) {
        const uint32_t base = sb0 + s * STAGE_B;
        const size_t k0 = (size_t)c << 5;
#pragma unroll
        for (int it = 0; it < 2; ++it) {
            int e = it * 256 + tid;
            int row = e >> 2, ch = e & 3;
            uint32_t d = base + row * ROW_B + ch * 16;
            size_t ga = ((size_t)(bm + row) * K + k0 + ch * 8) * 2;
            size_t gb = ((size_t)(bn + row) * K + k0 + ch * 8) * 2;
            CPA16(d,              (const char*)Ah + ga);
            CPA16(d + TILE_B,     (const char*)Al + ga);
            CPA16(d + 2 * TILE_B, (const char*)Bh + gb);
            CPA16(d + 3 * TILE_B, (const char*)Bl + gb);
        }
        CPA_COMMIT();
    };

    load_stage(0, 0);
    load_stage(1, 1);

    // per-warp ldmatrix base offsets (within a tile)
    const uint32_t a_off = (uint32_t)((wm * 64 + (lane & 15)) * ROW_B + (lane >> 4) * 16);
    const uint32_t b_off = (uint32_t)((wn * 32 + (lane & 7) + ((lane >> 4) << 3)) * ROW_B +
                                      ((lane >> 3) & 1) * 16);

    for (int c = 0; c < nc; ++c) {
        if (c + 1 < nc) CPA_WAIT1(); else CPA_WAIT0();
        __syncthreads();
        if (c + 2 < nc) load_stage(c + 2, (c + 2) % 3);

        const uint32_t base = sb0 + (c % 3) * STAGE_B;
        const uint32_t ab = base + a_off;
        const uint32_t bb = base + 2 * TILE_B + b_off;
#pragma unroll
        for (int ks = 0; ks < 2; ++ks) {
            uint32_t ah[4][4], al[4][4], bh[2][4], bl[2][4];
#pragma unroll
            for (int mf = 0; mf < 4; ++mf) ldsm4(ah[mf], ab + mf * 16 * ROW_B + ks * 32);
#pragma unroll
            for (int nf = 0; nf < 2; ++nf) ldsm4(bh[nf], bb + nf * 16 * ROW_B + ks * 32);
#pragma unroll
            for (int nf = 0; nf < 2; ++nf) ldsm4(bl[nf], bb + TILE_B + nf * 16 * ROW_B + ks * 32);
#pragma unroll
            for (int mf = 0; mf < 4; ++mf) ldsm4(al[mf], ab + TILE_B + mf * 16 * ROW_B + ks * 32);
            // pass 0: Ah * Bh
#pragma unroll
            for (int mf = 0; mf < 4; ++mf)
#pragma unroll
                for (int nf = 0; nf < 2; ++nf)
#pragma unroll
                    for (int sub = 0; sub < 2; ++sub)
                        mma16816(acc[mf][nf * 2 + sub], ah[mf],
                                 bh[nf][sub * 2], bh[nf][sub * 2 + 1]);
            // pass 1: Ah * Bl
#pragma unroll
            for (int mf = 0; mf < 4; ++mf)
#pragma unroll
                for (int nf = 0; nf < 2; ++nf)
#pragma unroll
                    for (int sub = 0; sub < 2; ++sub)
                        mma16816(acc[mf][nf * 2 + sub], ah[mf],
                                 bl[nf][sub * 2], bl[nf][sub * 2 + 1]);
            // pass 2: Al * Bh
#pragma unroll
            for (int mf = 0; mf < 4; ++mf)
#pragma unroll
                for (int nf = 0; nf < 2; ++nf)
#pragma unroll
                    for (int sub = 0; sub < 2; ++sub)
                        mma16816(acc[mf][nf * 2 + sub], al[mf],
                                 bh[nf][sub * 2], bh[nf][sub * 2 + 1]);
        }
    }

    // epilogue straight from fragments
#pragma unroll
    for (int mf = 0; mf < 4; ++mf) {
#pragma unroll
        for (int nf8 = 0; nf8 < 4; ++nf8) {
            int row = bm + wm * 64 + mf * 16 + (lane >> 2);
            int col = bn + wn * 32 + nf8 * 8 + (lane & 3) * 2;
            float b0 = bias[col], b1 = bias[col + 1];
#pragma unroll
            for (int half = 0; half < 2; ++half) {
                int r = row + half * 8;
                float v0 = acc[mf][nf8][half * 2 + 0] + b0;
                float v1 = acc[mf][nf8][half * 2 + 1] + b1;
                if (GELU) { v0 = v0 * normcdff(v0); v1 = v1 * normcdff(v1); }
                size_t o = (size_t)r * N + col;
                if (OUTMODE == 0) {
                    *(float2*)(Cf + o) = make_float2(v0, v1);
                } else {
                    __nv_bfloat16 h0, l0, h1, l1;
                    split2(v0, h0, l0); split2(v1, h1, l1);
                    *(__nv_bfloat162*)(Ch + o) = __nv_bfloat162(h0, h1);
                    *(__nv_bfloat162*)(Cl + o) = __nv_bfloat162(l0, l1);
                }
            }
        }
    }
}

// ---------------- weight fp32 -> (hi,lo) bf16 ----------------
__global__ void cvtw(const float* __restrict__ w, __nv_bfloat16* __restrict__ h,
                     __nv_bfloat16* __restrict__ l, int n) {
    int i = blockIdx.x * 256 + threadIdx.x;
    if (i < n) {
        __nv_bfloat16 hh, ll;
        split2(w[i], hh, ll);
        h[i] = hh; l[i] = ll;
    }
}

// (b,h,w) -> token index T in shifted-window order
__device__ __forceinline__ int src_to_token(int b, int h, int w) {
    int hs = (h + 60) & 63, ws = (w + 60) & 63;
    return ((b * 8 + (hs >> 3)) * 8 + (ws >> 3)) * 64 + (hs & 7) * 8 + (ws & 7);
}

// ---------------- LN1 + shift + window partition -> bf16 hi/lo ----------------
// one block per (b,h) row: coalesced x reads via smem tile [256c][64w+pad]
#define LN_SMEM (256 * 65 * 4)
__global__ __launch_bounds__(256)
void ln1_part(const float* __restrict__ x,
              const float* __restrict__ g, const float* __restrict__ bb,
              __nv_bfloat16* __restrict__ oh, __nv_bfloat16* __restrict__ ol) {
    extern __shared__ float xs[];  // [256][65]
    int b = blockIdx.x >> 6, h = blockIdx.x & 63;
    int tid = threadIdx.x;
    const float* xp = x + (size_t)b * 1048576 + h * 64;
#pragma unroll
    for (int it = 0; it < 64; ++it) {
        int e = it * 256 + tid;
        int c = e >> 6, w = e & 63;
        xs[c * 65 + w] = xp[(size_t)c * 4096 + w];
    }
    __syncthreads();
    int warp = tid >> 5, lane = tid & 31;
#pragma unroll 1
    for (int t = 0; t < 8; ++t) {
        int w = t * 8 + warp;
        float v[8]; float s = 0.f;
#pragma unroll
        for (int k = 0; k < 8; k++) { v[k] = xs[(k * 32 + lane) * 65 + w]; s += v[k]; }
#pragma unroll
        for (int o = 16; o; o >>= 1) s += __shfl_xor_sync(0xffffffffu, s, o);
        float mu = s * 0.00390625f;
        float q = 0.f;
#pragma unroll
        for (int k = 0; k < 8; k++) { float d = v[k] - mu; q += d * d; }
#pragma unroll
        for (int o = 16; o; o >>= 1) q += __shfl_xor_sync(0xffffffffu, q, o);
        float rs = rsqrtf(q * 0.00390625f + 1e-6f);
        size_t tb = (size_t)src_to_token(b, h, w) * 256;
#pragma unroll
        for (int k = 0; k < 8; k++) {
            int c = k * 32 + lane;
            float val = (v[k] - mu) * rs * g[c] + bb[c];
            __nv_bfloat16 hh, ll; split2(val, hh, ll);
            oh[tb + c] = hh; ol[tb + c] = ll;
        }
    }
}

// ---------------- attention: one block per (window, head) ----------------
__global__ __launch_bounds__(256)
void attn_kernel(const float* __restrict__ qkv,
                 __nv_bfloat16* __restrict__ oh, __nv_bfloat16* __restrict__ ol) {
    __shared__ float Qs[64][33], Ks[64][33], Vs[64][33];
    __shared__ float S[64][65];
    __shared__ float rinv[64];
    int win = blockIdx.x, head = blockIdx.y;
    int tid = threadIdx.x;
    size_t base = (size_t)win * 64 * 768 + head * 32;
#pragma unroll
    for (int e = tid; e < 2048; e += 256) {
        int i = e >> 5, d = e & 31;
        size_t row = base + (size_t)i * 768 + d;
        Qs[i][d] = qkv[row];
        Ks[i][d] = qkv[row + 256];
        Vs[i][d] = qkv[row + 512];
    }
    __syncthreads();
    const float scale = 0.17677669529663687f;  // 1/sqrt(32)
#pragma unroll
    for (int e = tid; e < 4096; e += 256) {
        int i = e >> 6, j = e & 63;
        float s = 0.f;
#pragma unroll
        for (int d = 0; d < 32; ++d) s += Qs[i][d] * Ks[j][d];
        S[i][j] = s * scale;
    }
    __syncthreads();
    if (tid < 64) {
        float m = -1e30f;
        for (int j = 0; j < 64; ++j) m = fmaxf(m, S[tid][j]);
        float sum = 0.f;
        for (int j = 0; j < 64; ++j) { float e = expf(S[tid][j] - m); S[tid][j] = e; sum += e; }
        rinv[tid] = 1.f / sum;
    }
    __syncthreads();
#pragma unroll
    for (int e = tid; e < 2048; e += 256) {
        int i = e >> 5, d = e & 31;
        float s = 0.f;
#pragma unroll
        for (int j = 0; j < 64; ++j) s += S[i][j] * Vs[j][d];
        float val = s * rinv[i];
        __nv_bfloat16 hh, ll; split2(val, hh, ll);
        size_t o = (size_t)(win * 64 + i) * 256 + head * 32 + d;
        oh[o] = hh; ol[o] = ll;
    }
}

// ---------------- window reverse + residual + LN2 ----------------
// one block per (b,h) row: coalesced x reads via smem tile
__global__ __launch_bounds__(256)
void resid_ln2(const float* __restrict__ x, const float* __restrict__ a,
               const float* __restrict__ g, const float* __restrict__ bb,
               float* __restrict__ yout,
               __nv_bfloat16* __restrict__ zh, __nv_bfloat16* __restrict__ zl) {
    extern __shared__ float xs[];  // [256][65]
    int b = blockIdx.x >> 6, h = blockIdx.x & 63;
    int tid = threadIdx.x;
    const float* xp = x + (size_t)b * 1048576 + h * 64;
#pragma unroll
    for (int it = 0; it < 64; ++it) {
        int e = it * 256 + tid;
        int c = e >> 6, w = e & 63;
        xs[c * 65 + w] = xp[(size_t)c * 4096 + w];
    }
    __syncthreads();
    int warp = tid >> 5, lane = tid & 31;
#pragma unroll 1
    for (int t = 0; t < 8; ++t) {
        int w = t * 8 + warp;
        size_t tb = (size_t)src_to_token(b, h, w) * 256;
        float v[8]; float s = 0.f;
#pragma unroll
        for (int k = 0; k < 8; k++) {
            int c = k * 32 + lane;
            v[k] = xs[c * 65 + w] + a[tb + c];
            s += v[k];
        }
#pragma unroll
        for (int o = 16; o; o >>= 1) s += __shfl_xor_sync(0xffffffffu, s, o);
        float mu = s * 0.00390625f;
        float q = 0.f;
#pragma unroll
        for (int k = 0; k < 8; k++) { float d = v[k] - mu; q += d * d; }
#pragma unroll
        for (int o = 16; o; o >>= 1) q += __shfl_xor_sync(0xffffffffu, q, o);
        float rs = rsqrtf(q * 0.00390625f + 1e-6f);
#pragma unroll
        for (int k = 0; k < 8; k++) {
            int c = k * 32 + lane;
            yout[tb + c] = v[k];
            float val = (v[k] - mu) * rs * g[c] + bb[c];
            __nv_bfloat16 hh, ll; split2(val, hh, ll);
            zh[tb + c] = hh; zl[tb + c] = ll;
        }
    }
}

// ---------------- final: out[b,c,h,w] = y_tok + mlp_tok, smem transpose ----
#define FIN_SMEM (64 * 257 * 4)
__global__ __launch_bounds__(256)
void final_add(const float* __restrict__ y, const float* __restrict__ m,
               float* __restrict__ out) {
    extern __shared__ float ss[];  // [64 tokens][257]
    int b = blockIdx.x >> 6, h = blockIdx.x & 63;
    int tid = threadIdx.x;
    int warp = tid >> 5, lane = tid & 31;
#pragma unroll 1
    for (int t = 0; t < 8; ++t) {
        int w = t * 8 + warp;
        size_t tb = (size_t)src_to_token(b, h, w) * 256;
#pragma unroll
        for (int k = 0; k < 8; k++) {
            int c = k * 32 + lane;
            ss[w * 257 + c] = y[tb + c] + m[tb + c];
        }
    }
    __syncthreads();
    float* op = out + (size_t)b * 1048576 + h * 64;
#pragma unroll
    for (int it = 0; it < 64; ++it) {
        int e = it * 256 + tid;
        int c = e >> 6, w = e & 63;
        op[(size_t)c * 4096 + w] = ss[w * 257 + c];
    }
}

// ---------------- launch ----------------
extern "C" void kernel_launch(void* const* d_in, const int* in_sizes, int n_in,
                              void* d_out, int out_size) {
    const float* x      = (const float*)d_in[0];
    const float* n1g    = (const float*)d_in[1];
    const float* n1b    = (const float*)d_in[2];
    const float* in_w   = (const float*)d_in[3];
    const float* in_b   = (const float*)d_in[4];
    const float* out_w  = (const float*)d_in[5];
    const float* out_b  = (const float*)d_in[6];
    const float* proj_w = (const float*)d_in[7];
    const float* proj_b = (const float*)d_in[8];
    const float* n2g    = (const float*)d_in[9];
    const float* n2b    = (const float*)d_in[10];
    const float* fc1_w  = (const float*)d_in[11];
    const float* fc1_b  = (const float*)d_in[12];
    const float* fc2_w  = (const float*)d_in[13];
    const float* fc2_b  = (const float*)d_in[14];
    float* out = (float*)d_out;

    __nv_bfloat16 *xnh, *xnl, *ath, *atl, *tmph, *tmpl, *zh, *zl, *h1h, *h1l, *wh, *wl;
    float *qkv, *attn2, *yb, *mlp;
    cudaGetSymbolAddress((void**)&xnh,   g_xn_h);
    cudaGetSymbolAddress((void**)&xnl,   g_xn_l);
    cudaGetSymbolAddress((void**)&qkv,   g_qkv);
    cudaGetSymbolAddress((void**)&ath,   g_at_h);
    cudaGetSymbolAddress((void**)&atl,   g_at_l);
    cudaGetSymbolAddress((void**)&tmph,  g_tmp_h);
    cudaGetSymbolAddress((void**)&tmpl,  g_tmp_l);
    cudaGetSymbolAddress((void**)&attn2, g_attn2);
    cudaGetSymbolAddress((void**)&yb,    g_y);
    cudaGetSymbolAddress((void**)&zh,    g_z_h);
    cudaGetSymbolAddress((void**)&zl,    g_z_l);
    cudaGetSymbolAddress((void**)&h1h,   g_h1_h);
    cudaGetSymbolAddress((void**)&h1l,   g_h1_l);
    cudaGetSymbolAddress((void**)&mlp,   g_mlp);
    cudaGetSymbolAddress((void**)&wh,    g_w_h);
    cudaGetSymbolAddress((void**)&wl,    g_w_l);

    cudaFuncSetAttribute(mma_gemm<0, false>, cudaFuncAttributeMaxDynamicSharedMemorySize, GEMM_SMEM);
    cudaFuncSetAttribute(mma_gemm<1, false>, cudaFuncAttributeMaxDynamicSharedMemorySize, GEMM_SMEM);
    cudaFuncSetAttribute(mma_gemm<1, true >, cudaFuncAttributeMaxDynamicSharedMemorySize, GEMM_SMEM);
    cudaFuncSetAttribute(ln1_part,  cudaFuncAttributeMaxDynamicSharedMemorySize, LN_SMEM);
    cudaFuncSetAttribute(resid_ln2, cudaFuncAttributeMaxDynamicSharedMemorySize, LN_SMEM);
    cudaFuncSetAttribute(final_add, cudaFuncAttributeMaxDynamicSharedMemorySize, FIN_SMEM);

    // weight conversion (deterministic, tiny)
    cvtw<<<768,  256>>>(in_w,   wh + OFF_INW,  wl + OFF_INW,  196608);
    cvtw<<<256,  256>>>(out_w,  wh + OFF_OUTW, wl + OFF_OUTW, 65536);
    cvtw<<<256,  256>>>(proj_w, wh + OFF_PRJW, wl + OFF_PRJW, 65536);
    cvtw<<<1024, 256>>>(fc1_w,  wh + OFF_FC1W, wl + OFF_FC1W, 262144);
    cvtw<<<1024, 256>>>(fc2_w,  wh + OFF_FC2W, wl + OFF_FC2W, 262144);

    ln1_part<<<1024, 256, LN_SMEM>>>(x, n1g, n1b, xnh, xnl);

    // qkv: [65536,768] = xn @ in_w^T
    mma_gemm<0, false><<<dim3(6, 512), 256, GEMM_SMEM>>>(
        xnh, xnl, wh + OFF_INW, wl + OFF_INW, in_b, qkv, nullptr, nullptr, 768, 256);

    attn_kernel<<<dim3(1024, 8), 256>>>(qkv, ath, atl);

    // out_w: [65536,256]
    mma_gemm<1, false><<<dim3(2, 512), 256, GEMM_SMEM>>>(
        ath, atl, wh + OFF_OUTW, wl + OFF_OUTW, out_b, nullptr, tmph, tmpl, 256, 256);

    // proj_w: [65536,256]
    mma_gemm<0, false><<<dim3(2, 512), 256, GEMM_SMEM>>>(
        tmph, tmpl, wh + OFF_PRJW, wl + OFF_PRJW, proj_b, attn2, nullptr, nullptr, 256, 256);

    resid_ln2<<<1024, 256, LN_SMEM>>>(x, attn2, n2g, n2b, yb, zh, zl);

    // fc1 + gelu: [65536,1024]
    mma_gemm<1, true><<<dim3(8, 512), 256, GEMM_SMEM>>>(
        zh, zl, wh + OFF_FC1W, wl + OFF_FC1W, fc1_b, nullptr, h1h, h1l, 1024, 256);

    // fc2: [65536,256], K=1024
    mma_gemm<0, false><<<dim3(2, 512), 256, GEMM_SMEM>>>(
        h1h, h1l, wh + OFF_FC2W, wl + OFF_FC2W, fc2_b, mlp, nullptr, nullptr, 256, 1024);

    final_add<<<1024, 256, FIN_SMEM>>>(yb, mlp, out);
}

// round 9
// speedup vs baseline: 1.6055x; 1.6055x over previous
#include <cuda_runtime.h>
#include <cuda_bf16.h>
#include <cstdint>
#include <cstddef>

#define NTOK 65536  // 16 * 64 * 64 tokens

// ---------------- scratch (no allocations allowed) ----------------
__device__ __nv_bfloat16 g_xn_h [(size_t)NTOK * 256];
__device__ __nv_bfloat16 g_xn_l [(size_t)NTOK * 256];
__device__ float         g_qkv  [(size_t)NTOK * 768];
__device__ __nv_bfloat16 g_at_h [(size_t)NTOK * 256];
__device__ __nv_bfloat16 g_at_l [(size_t)NTOK * 256];
__device__ __nv_bfloat16 g_tmp_h[(size_t)NTOK * 256];
__device__ __nv_bfloat16 g_tmp_l[(size_t)NTOK * 256];
__device__ float         g_attn2[(size_t)NTOK * 256];
__device__ float         g_y    [(size_t)NTOK * 256];
__device__ __nv_bfloat16 g_z_h  [(size_t)NTOK * 256];
__device__ __nv_bfloat16 g_z_l  [(size_t)NTOK * 256];
__device__ __nv_bfloat16 g_h1_h [(size_t)NTOK * 1024];
__device__ __nv_bfloat16 g_h1_l [(size_t)NTOK * 1024];
__device__ float         g_mlp  [(size_t)NTOK * 256];
// packed bf16 hi/lo weights: in_w(196608) out_w(65536) proj_w(65536) fc1_w(262144) fc2_w(262144)
__device__ __nv_bfloat16 g_w_h[851968];
__device__ __nv_bfloat16 g_w_l[851968];

#define OFF_INW  0
#define OFF_OUTW 196608
#define OFF_PRJW 262144
#define OFF_FC1W 327680
#define OFF_FC2W 589824

// ---------------- small helpers ----------------
__device__ __forceinline__ void split2(float v, __nv_bfloat16& h, __nv_bfloat16& l) {
    h = __float2bfloat16(v);
    l = __float2bfloat16(v - __bfloat162float(h));
}

__device__ __forceinline__ uint32_t smem_u32(const void* p) {
    uint32_t a;
    asm("{ .reg .u64 t; cvta.to.shared.u64 t, %1; cvt.u32.u64 %0, t; }" : "=r"(a) : "l"(p));
    return a;
}

#define CPA16(dst, src) \
    asm volatile("cp.async.cg.shared.global [%0], [%1], 16;\n" :: "r"(dst), "l"(src))
#define CPA_COMMIT() asm volatile("cp.async.commit_group;\n" ::: "memory")
#define CPA_WAIT1()  asm volatile("cp.async.wait_group 1;\n" ::: "memory")
#define CPA_WAIT0()  asm volatile("cp.async.wait_group 0;\n" ::: "memory")

__device__ __forceinline__ void ldsm4(uint32_t* r, uint32_t addr) {
    asm volatile("ldmatrix.sync.aligned.m8n8.x4.shared.b16 {%0,%1,%2,%3}, [%4];\n"
                 : "=r"(r[0]), "=r"(r[1]), "=r"(r[2]), "=r"(r[3]) : "r"(addr));
}
__device__ __forceinline__ void mma16816(float* c, const uint32_t* a, uint32_t b0, uint32_t b1) {
    asm volatile(
        "mma.sync.aligned.m16n8k16.row.col.f32.bf16.bf16.f32 "
        "{%0,%1,%2,%3}, {%4,%5,%6,%7}, {%8,%9}, {%0,%1,%2,%3};\n"
        : "+f"(c[0]), "+f"(c[1]), "+f"(c[2]), "+f"(c[3])
        : "r"(a[0]), "r"(a[1]), "r"(a[2]), "r"(a[3]), "r"(b0), "r"(b1));
}

// ---------------- mma.sync split-bf16 GEMM (R7-proven mainloop) ----------------
// C[M,N] = A[M,K] @ B[N,K]^T + bias, A/B as (hi,lo) bf16 pairs; 3-pass split.
// Block 128x128, 8 warps (2x4), warp tile 64x32, BK=32, cp.async double buffer.
// smem tile: 128 rows x 80B (64B data + 16B pad) -> ldmatrix conflict-free.
// 80KB smem -> 2 CTAs/SM; two syncs/chunk lets co-resident CTAs overlap.
#define ROW_B       80
#define TILE_B      (128 * ROW_B)     // 10240
#define STAGE_B     (4 * TILE_B)      // Ah | Al | Bh | Bl = 40960
#define GEMM_SMEM   (2 * STAGE_B)     // 81920

template <int OUTMODE /*0=f32, 1=hilo*/, bool GELU>
__global__ __launch_bounds__(256)
void mma_gemm(const __nv_bfloat16* __restrict__ Ah, const __nv_bfloat16* __restrict__ Al,
              const __nv_bfloat16* __restrict__ Bh, const __nv_bfloat16* __restrict__ Bl,
              const float* __restrict__ bias,
              float* __restrict__ Cf,
              __nv_bfloat16* __restrict__ Ch, __nv_bfloat16* __restrict__ Cl,
              int N, int K) {
    extern __shared__ char smem[];
    const uint32_t sb0 = smem_u32(smem);
    const int tid = threadIdx.x, lane = tid & 31, wid = tid >> 5;
    const int wm = wid >> 2, wn = wid & 3;        // 2 x 4 warp grid
    const int bm = blockIdx.y * 128, bn = blockIdx.x * 128;

    float acc[4][4][4];
#pragma unroll
    for (int i = 0; i < 4; i++)
#pragma unroll
        for (int j = 0; j < 4; j++)
#pragma unroll
            for (int k = 0; k < 4; k++) acc[i][j][k] = 0.f;

    const int nc = K >> 5;  // BK=32 chunks

    auto load_stage = [&](int c, int s) {
        const uint32_t base = sb0 + s * STAGE_B;
        const size_t k0 = (size_t)c << 5;
#pragma unroll
        for (int it = 0; it < 2; ++it) {
            int e = it * 256 + tid;
            int row = e >> 2, ch = e & 3;
            uint32_t d = base + row * ROW_B + ch * 16;
            size_t ga = ((size_t)(bm + row) * K + k0 + ch * 8) * 2;
            size_t gb = ((size_t)(bn + row) * K + k0 + ch * 8) * 2;
            CPA16(d,              (const char*)Ah + ga);
            CPA16(d + TILE_B,     (const char*)Al + ga);
            CPA16(d + 2 * TILE_B, (const char*)Bh + gb);
            CPA16(d + 3 * TILE_B, (const char*)Bl + gb);
        }
        CPA_COMMIT();
    };

    load_stage(0, 0);

    // per-warp ldmatrix base offsets (within a tile)
    const uint32_t a_off = (uint32_t)((wm * 64 + (lane & 15)) * ROW_B + (lane >> 4) * 16);
    const uint32_t b_off = (uint32_t)((wn * 32 + (lane & 7) + ((lane >> 4) << 3)) * ROW_B +
                                      ((lane >> 3) & 1) * 16);

    for (int c = 0; c < nc; ++c) {
        const int s = c & 1;
        if (c + 1 < nc) { load_stage(c + 1, (c + 1) & 1); CPA_WAIT1(); }
        else            { CPA_WAIT0(); }
        __syncthreads();

        const uint32_t base = sb0 + s * STAGE_B;
        const uint32_t abase = base + a_off;
        const uint32_t bbase = base + 2 * TILE_B + b_off;
#pragma unroll
        for (int pass = 0; pass < 3; ++pass) {
            const uint32_t ab = abase + (pass == 2 ? TILE_B : 0);  // Al on pass2
            const uint32_t bb = bbase + (pass == 1 ? TILE_B : 0);  // Bl on pass1
#pragma unroll
            for (int ks = 0; ks < 2; ++ks) {
                uint32_t a[4][4], b[2][4];
#pragma unroll
                for (int mf = 0; mf < 4; ++mf) ldsm4(a[mf], ab + mf * 16 * ROW_B + ks * 32);
#pragma unroll
                for (int nf = 0; nf < 2; ++nf) ldsm4(b[nf], bb + nf * 16 * ROW_B + ks * 32);
#pragma unroll
                for (int mf = 0; mf < 4; ++mf)
#pragma unroll
                    for (int nf = 0; nf < 2; ++nf)
#pragma unroll
                        for (int sub = 0; sub < 2; ++sub)
                            mma16816(acc[mf][nf * 2 + sub], a[mf],
                                     b[nf][sub * 2], b[nf][sub * 2 + 1]);
            }
        }
        __syncthreads();
    }

    // epilogue straight from fragments
#pragma unroll
    for (int mf = 0; mf < 4; ++mf) {
#pragma unroll
        for (int nf8 = 0; nf8 < 4; ++nf8) {
            int row = bm + wm * 64 + mf * 16 + (lane >> 2);
            int col = bn + wn * 32 + nf8 * 8 + (lane & 3) * 2;
            float b0 = bias[col], b1 = bias[col + 1];
#pragma unroll
            for (int half = 0; half < 2; ++half) {
                int r = row + half * 8;
                float v0 = acc[mf][nf8][half * 2 + 0] + b0;
                float v1 = acc[mf][nf8][half * 2 + 1] + b1;
                if (GELU) { v0 = v0 * normcdff(v0); v1 = v1 * normcdff(v1); }
                size_t o = (size_t)r * N + col;
                if (OUTMODE == 0) {
                    *(float2*)(Cf + o) = make_float2(v0, v1);
                } else {
                    __nv_bfloat16 h0, l0, h1, l1;
                    split2(v0, h0, l0); split2(v1, h1, l1);
                    *(__nv_bfloat162*)(Ch + o) = __nv_bfloat162(h0, h1);
                    *(__nv_bfloat162*)(Cl + o) = __nv_bfloat162(l0, l1);
                }
            }
        }
    }
}

// ---------------- weight fp32 -> (hi,lo) bf16 ----------------
__global__ void cvtw(const float* __restrict__ w, __nv_bfloat16* __restrict__ h,
                     __nv_bfloat16* __restrict__ l, int n) {
    int i = blockIdx.x * 256 + threadIdx.x;
    if (i < n) {
        __nv_bfloat16 hh, ll;
        split2(w[i], hh, ll);
        h[i] = hh; l[i] = ll;
    }
}

// (b,h,w) -> token index T in shifted-window order
__device__ __forceinline__ int src_to_token(int b, int h, int w) {
    int hs = (h + 60) & 63, ws = (w + 60) & 63;
    return ((b * 8 + (hs >> 3)) * 8 + (ws >> 3)) * 64 + (hs & 7) * 8 + (ws & 7);
}

// ---------------- LN1 + shift + window partition -> bf16 hi/lo ----------------
// one block per (b,h) row: coalesced x reads via smem tile [256c][64w+pad]
#define LN_SMEM (256 * 65 * 4)
__global__ __launch_bounds__(256)
void ln1_part(const float* __restrict__ x,
              const float* __restrict__ g, const float* __restrict__ bb,
              __nv_bfloat16* __restrict__ oh, __nv_bfloat16* __restrict__ ol) {
    extern __shared__ float xs[];  // [256][65]
    int b = blockIdx.x >> 6, h = blockIdx.x & 63;
    int tid = threadIdx.x;
    const float* xp = x + (size_t)b * 1048576 + h * 64;
#pragma unroll
    for (int it = 0; it < 64; ++it) {
        int e = it * 256 + tid;
        int c = e >> 6, w = e & 63;
        xs[c * 65 + w] = xp[(size_t)c * 4096 + w];
    }
    __syncthreads();
    int warp = tid >> 5, lane = tid & 31;
#pragma unroll 1
    for (int t = 0; t < 8; ++t) {
        int w = t * 8 + warp;
        float v[8]; float s = 0.f;
#pragma unroll
        for (int k = 0; k < 8; k++) { v[k] = xs[(k * 32 + lane) * 65 + w]; s += v[k]; }
#pragma unroll
        for (int o = 16; o; o >>= 1) s += __shfl_xor_sync(0xffffffffu, s, o);
        float mu = s * 0.00390625f;
        float q = 0.f;
#pragma unroll
        for (int k = 0; k < 8; k++) { float d = v[k] - mu; q += d * d; }
#pragma unroll
        for (int o = 16; o; o >>= 1) q += __shfl_xor_sync(0xffffffffu, q, o);
        float rs = rsqrtf(q * 0.00390625f + 1e-6f);
        size_t tb = (size_t)src_to_token(b, h, w) * 256;
#pragma unroll
        for (int k = 0; k < 8; k++) {
            int c = k * 32 + lane;
            float val = (v[k] - mu) * rs * g[c] + bb[c];
            __nv_bfloat16 hh, ll; split2(val, hh, ll);
            oh[tb + c] = hh; ol[tb + c] = ll;
        }
    }
}

// ---------------- attention: one block per (window, head) ----------------
__global__ __launch_bounds__(256)
void attn_kernel(const float* __restrict__ qkv,
                 __nv_bfloat16* __restrict__ oh, __nv_bfloat16* __restrict__ ol) {
    __shared__ float Qs[64][33], Ks[64][33], Vs[64][33];
    __shared__ float S[64][65];
    __shared__ float rinv[64];
    int win = blockIdx.x, head = blockIdx.y;
    int tid = threadIdx.x;
    size_t base = (size_t)win * 64 * 768 + head * 32;
#pragma unroll
    for (int e = tid; e < 2048; e += 256) {
        int i = e >> 5, d = e & 31;
        size_t row = base + (size_t)i * 768 + d;
        Qs[i][d] = qkv[row];
        Ks[i][d] = qkv[row + 256];
        Vs[i][d] = qkv[row + 512];
    }
    __syncthreads();
    const float scale = 0.17677669529663687f;  // 1/sqrt(32)
#pragma unroll
    for (int e = tid; e < 4096; e += 256) {
        int i = e >> 6, j = e & 63;
        float s = 0.f;
#pragma unroll
        for (int d = 0; d < 32; ++d) s += Qs[i][d] * Ks[j][d];
        S[i][j] = s * scale;
    }
    __syncthreads();
    if (tid < 64) {
        float m = -1e30f;
        for (int j = 0; j < 64; ++j) m = fmaxf(m, S[tid][j]);
        float sum = 0.f;
        for (int j = 0; j < 64; ++j) { float e = expf(S[tid][j] - m); S[tid][j] = e; sum += e; }
        rinv[tid] = 1.f / sum;
    }
    __syncthreads();
#pragma unroll
    for (int e = tid; e < 2048; e += 256) {
        int i = e >> 5, d = e & 31;
        float s = 0.f;
#pragma unroll
        for (int j = 0; j < 64; ++j) s += S[i][j] * Vs[j][d];
        float val = s * rinv[i];
        __nv_bfloat16 hh, ll; split2(val, hh, ll);
        size_t o = (size_t)(win * 64 + i) * 256 + head * 32 + d;
        oh[o] = hh; ol[o] = ll;
    }
}

// ---------------- window reverse + residual + LN2 ----------------
// one block per (b,h) row: coalesced x reads via smem tile
__global__ __launch_bounds__(256)
void resid_ln2(const float* __restrict__ x, const float* __restrict__ a,
               const float* __restrict__ g, const float* __restrict__ bb,
               float* __restrict__ yout,
               __nv_bfloat16* __restrict__ zh, __nv_bfloat16* __restrict__ zl) {
    extern __shared__ float xs[];  // [256][65]
    int b = blockIdx.x >> 6, h = blockIdx.x & 63;
    int tid = threadIdx.x;
    const float* xp = x + (size_t)b * 1048576 + h * 64;
#pragma unroll
    for (int it = 0; it < 64; ++it) {
        int e = it * 256 + tid;
        int c = e >> 6, w = e & 63;
        xs[c * 65 + w] = xp[(size_t)c * 4096 + w];
    }
    __syncthreads();
    int warp = tid >> 5, lane = tid & 31;
#pragma unroll 1
    for (int t = 0; t < 8; ++t) {
        int w = t * 8 + warp;
        size_t tb = (size_t)src_to_token(b, h, w) * 256;
        float v[8]; float s = 0.f;
#pragma unroll
        for (int k = 0; k < 8; k++) {
            int c = k * 32 + lane;
            v[k] = xs[c * 65 + w] + a[tb + c];
            s += v[k];
        }
#pragma unroll
        for (int o = 16; o; o >>= 1) s += __shfl_xor_sync(0xffffffffu, s, o);
        float mu = s * 0.00390625f;
        float q = 0.f;
#pragma unroll
        for (int k = 0; k < 8; k++) { float d = v[k] - mu; q += d * d; }
#pragma unroll
        for (int o = 16; o; o >>= 1) q += __shfl_xor_sync(0xffffffffu, q, o);
        float rs = rsqrtf(q * 0.00390625f + 1e-6f);
#pragma unroll
        for (int k = 0; k < 8; k++) {
            int c = k * 32 + lane;
            yout[tb + c] = v[k];
            float val = (v[k] - mu) * rs * g[c] + bb[c];
            __nv_bfloat16 hh, ll; split2(val, hh, ll);
            zh[tb + c] = hh; zl[tb + c] = ll;
        }
    }
}

// ---------------- final: out[b,c,h,w] = y_tok + mlp_tok, smem transpose ----
#define FIN_SMEM (64 * 257 * 4)
__global__ __launch_bounds__(256)
void final_add(const float* __restrict__ y, const float* __restrict__ m,
               float* __restrict__ out) {
    extern __shared__ float ss[];  // [64 tokens][257]
    int b = blockIdx.x >> 6, h = blockIdx.x & 63;
    int tid = threadIdx.x;
    int warp = tid >> 5, lane = tid & 31;
#pragma unroll 1
    for (int t = 0; t < 8; ++t) {
        int w = t * 8 + warp;
        size_t tb = (size_t)src_to_token(b, h, w) * 256;
#pragma unroll
        for (int k = 0; k < 8; k++) {
            int c = k * 32 + lane;
            ss[w * 257 + c] = y[tb + c] + m[tb + c];
        }
    }
    __syncthreads();
    float* op = out + (size_t)b * 1048576 + h * 64;
#pragma unroll
    for (int it = 0; it < 64; ++it) {
        int e = it * 256 + tid;
        int c = e >> 6, w = e & 63;
        op[(size_t)c * 4096 + w] = ss[w * 257 + c];
    }
}

// ---------------- launch ----------------
extern "C" void kernel_launch(void* const* d_in, const int* in_sizes, int n_in,
                              void* d_out, int out_size) {
    const float* x      = (const float*)d_in[0];
    const float* n1g    = (const float*)d_in[1];
    const float* n1b    = (const float*)d_in[2];
    const float* in_w   = (const float*)d_in[3];
    const float* in_b   = (const float*)d_in[4];
    const float* out_w  = (const float*)d_in[5];
    const float* out_b  = (const float*)d_in[6];
    const float* proj_w = (const float*)d_in[7];
    const float* proj_b = (const float*)d_in[8];
    const float* n2g    = (const float*)d_in[9];
    const float* n2b    = (const float*)d_in[10];
    const float* fc1_w  = (const float*)d_in[11];
    const float* fc1_b  = (const float*)d_in[12];
    const float* fc2_w  = (const float*)d_in[13];
    const float* fc2_b  = (const float*)d_in[14];
    float* out = (float*)d_out;

    __nv_bfloat16 *xnh, *xnl, *ath, *atl, *tmph, *tmpl, *zh, *zl, *h1h, *h1l, *wh, *wl;
    float *qkv, *attn2, *yb, *mlp;
    cudaGetSymbolAddress((void**)&xnh,   g_xn_h);
    cudaGetSymbolAddress((void**)&xnl,   g_xn_l);
    cudaGetSymbolAddress((void**)&qkv,   g_qkv);
    cudaGetSymbolAddress((void**)&ath,   g_at_h);
    cudaGetSymbolAddress((void**)&atl,   g_at_l);
    cudaGetSymbolAddress((void**)&tmph,  g_tmp_h);
    cudaGetSymbolAddress((void**)&tmpl,  g_tmp_l);
    cudaGetSymbolAddress((void**)&attn2, g_attn2);
    cudaGetSymbolAddress((void**)&yb,    g_y);
    cudaGetSymbolAddress((void**)&zh,    g_z_h);
    cudaGetSymbolAddress((void**)&zl,    g_z_l);
    cudaGetSymbolAddress((void**)&h1h,   g_h1_h);
    cudaGetSymbolAddress((void**)&h1l,   g_h1_l);
    cudaGetSymbolAddress((void**)&mlp,   g_mlp);
    cudaGetSymbolAddress((void**)&wh,    g_w_h);
    cudaGetSymbolAddress((void**)&wl,    g_w_l);

    cudaFuncSetAttribute(mma_gemm<0, false>, cudaFuncAttributeMaxDynamicSharedMemorySize, GEMM_SMEM);
    cudaFuncSetAttribute(mma_gemm<1, false>, cudaFuncAttributeMaxDynamicSharedMemorySize, GEMM_SMEM);
    cudaFuncSetAttribute(mma_gemm<1, true >, cudaFuncAttributeMaxDynamicSharedMemorySize, GEMM_SMEM);
    cudaFuncSetAttribute(ln1_part,  cudaFuncAttributeMaxDynamicSharedMemorySize, LN_SMEM);
    cudaFuncSetAttribute(resid_ln2, cudaFuncAttributeMaxDynamicSharedMemorySize, LN_SMEM);
    cudaFuncSetAttribute(final_add, cudaFuncAttributeMaxDynamicSharedMemorySize, FIN_SMEM);

    // weight conversion (deterministic, tiny)
    cvtw<<<768,  256>>>(in_w,   wh + OFF_INW,  wl + OFF_INW,  196608);
    cvtw<<<256,  256>>>(out_w,  wh + OFF_OUTW, wl + OFF_OUTW, 65536);
    cvtw<<<256,  256>>>(proj_w, wh + OFF_PRJW, wl + OFF_PRJW, 65536);
    cvtw<<<1024, 256>>>(fc1_w,  wh + OFF_FC1W, wl + OFF_FC1W, 262144);
    cvtw<<<1024, 256>>>(fc2_w,  wh + OFF_FC2W, wl + OFF_FC2W, 262144);

    ln1_part<<<1024, 256, LN_SMEM>>>(x, n1g, n1b, xnh, xnl);

    // qkv: [65536,768] = xn @ in_w^T
    mma_gemm<0, false><<<dim3(6, 512), 256, GEMM_SMEM>>>(
        xnh, xnl, wh + OFF_INW, wl + OFF_INW, in_b, qkv, nullptr, nullptr, 768, 256);

    attn_kernel<<<dim3(1024, 8), 256>>>(qkv, ath, atl);

    // out_w: [65536,256]
    mma_gemm<1, false><<<dim3(2, 512), 256, GEMM_SMEM>>>(
        ath, atl, wh + OFF_OUTW, wl + OFF_OUTW, out_b, nullptr, tmph, tmpl, 256, 256);

    // proj_w: [65536,256]
    mma_gemm<0, false><<<dim3(2, 512), 256, GEMM_SMEM>>>(
        tmph, tmpl, wh + OFF_PRJW, wl + OFF_PRJW, proj_b, attn2, nullptr, nullptr, 256, 256);

    resid_ln2<<<1024, 256, LN_SMEM>>>(x, attn2, n2g, n2b, yb, zh, zl);

    // fc1 + gelu: [65536,1024]
    mma_gemm<1, true><<<dim3(8, 512), 256, GEMM_SMEM>>>(
        zh, zl, wh + OFF_FC1W, wl + OFF_FC1W, fc1_b, nullptr, h1h, h1l, 1024, 256);

    // fc2: [65536,256], K=1024
    mma_gemm<0, false><<<dim3(2, 512), 256, GEMM_SMEM>>>(
        h1h, h1l, wh + OFF_FC2W, wl + OFF_FC2W, fc2_b, mlp, nullptr, nullptr, 256, 1024);

    final_add<<<1024, 256, FIN_SMEM>>>(yb, mlp, out);
}

// round 10
// speedup vs baseline: 2.0125x; 1.2535x over previous
#include <cuda_runtime.h>
#include <cuda_bf16.h>
#include <cstdint>
#include <cstddef>

#define NTOK 65536  // 16 * 64 * 64 tokens

// ---------------- scratch (no allocations allowed) ----------------
__device__ __nv_bfloat16 g_xn_h [(size_t)NTOK * 256];
__device__ __nv_bfloat16 g_xn_l [(size_t)NTOK * 256];
__device__ float         g_qkv  [(size_t)NTOK * 768];
__device__ __nv_bfloat16 g_at_h [(size_t)NTOK * 256];
__device__ __nv_bfloat16 g_at_l [(size_t)NTOK * 256];
__device__ float         g_attn2[(size_t)NTOK * 256];
__device__ float         g_y    [(size_t)NTOK * 256];
__device__ __nv_bfloat16 g_z_h  [(size_t)NTOK * 256];
__device__ __nv_bfloat16 g_z_l  [(size_t)NTOK * 256];
__device__ __nv_bfloat16 g_h1_h [(size_t)NTOK * 1024];
__device__ __nv_bfloat16 g_h1_l [(size_t)NTOK * 1024];
__device__ float         g_mlp  [(size_t)NTOK * 256];
// packed bf16 hi/lo weights: in_w(196608) comb_w(65536) fc1_w(262144) fc2_w(262144)
__device__ __nv_bfloat16 g_w_h[786432];
__device__ __nv_bfloat16 g_w_l[786432];
__device__ float         g_bcomb[256];

#define OFF_INW  0
#define OFF_CMBW 196608
#define OFF_FC1W 262144
#define OFF_FC2W 524288

// ---------------- small helpers ----------------
__device__ __forceinline__ void split2(float v, __nv_bfloat16& h, __nv_bfloat16& l) {
    h = __float2bfloat16(v);
    l = __float2bfloat16(v - __bfloat162float(h));
}

__device__ __forceinline__ uint32_t smem_u32(const void* p) {
    uint32_t a;
    asm("{ .reg .u64 t; cvta.to.shared.u64 t, %1; cvt.u32.u64 %0, t; }" : "=r"(a) : "l"(p));
    return a;
}

#define CPA16(dst, src) \
    asm volatile("cp.async.cg.shared.global [%0], [%1], 16;\n" :: "r"(dst), "l"(src))
#define CPA_COMMIT() asm volatile("cp.async.commit_group;\n" ::: "memory")
#define CPA_WAIT1()  asm volatile("cp.async.wait_group 1;\n" ::: "memory")
#define CPA_WAIT0()  asm volatile("cp.async.wait_group 0;\n" ::: "memory")

__device__ __forceinline__ void ldsm4(uint32_t* r, uint32_t addr) {
    asm volatile("ldmatrix.sync.aligned.m8n8.x4.shared.b16 {%0,%1,%2,%3}, [%4];\n"
                 : "=r"(r[0]), "=r"(r[1]), "=r"(r[2]), "=r"(r[3]) : "r"(addr));
}
__device__ __forceinline__ void mma16816(float* c, const uint32_t* a, uint32_t b0, uint32_t b1) {
    asm volatile(
        "mma.sync.aligned.m16n8k16.row.col.f32.bf16.bf16.f32 "
        "{%0,%1,%2,%3}, {%4,%5,%6,%7}, {%8,%9}, {%0,%1,%2,%3};\n"
        : "+f"(c[0]), "+f"(c[1]), "+f"(c[2]), "+f"(c[3])
        : "r"(a[0]), "r"(a[1]), "r"(a[2]), "r"(a[3]), "r"(b0), "r"(b1));
}

// ---------------- mma.sync split-bf16 GEMM ----------------
// C[M,N] = A[M,K] @ B[N,K]^T + bias, A/B as (hi,lo) bf16 pairs; 3-pass split.
// Block 128x128, 8 warps (2x4), warp tile 64x32, BK=32, cp.async double buffer.
// smem tile: 128 rows x 80B -> ldmatrix conflict-free. 80KB smem, forced 2 CTA/SM.
// Inner loop: 12 ldsm.x4 per ks (Ah,Bh,Bl then reuse a-regs for Al), frag peak 32 regs.
#define ROW_B       80
#define TILE_B      (128 * ROW_B)     // 10240
#define STAGE_B     (4 * TILE_B)      // Ah | Al | Bh | Bl = 40960
#define GEMM_SMEM   (2 * STAGE_B)     // 81920

template <int OUTMODE /*0=f32, 1=hilo*/, bool GELU>
__global__ __launch_bounds__(256, 2)
void mma_gemm(const __nv_bfloat16* __restrict__ Ah, const __nv_bfloat16* __restrict__ Al,
              const __nv_bfloat16* __restrict__ Bh, const __nv_bfloat16* __restrict__ Bl,
              const float* __restrict__ bias,
              float* __restrict__ Cf,
              __nv_bfloat16* __restrict__ Ch, __nv_bfloat16* __restrict__ Cl,
              int N, int K) {
    extern __shared__ char smem[];
    const uint32_t sb0 = smem_u32(smem);
    const int tid = threadIdx.x, lane = tid & 31, wid = tid >> 5;
    const int wm = wid >> 2, wn = wid & 3;        // 2 x 4 warp grid
    const int bm = blockIdx.y * 128, bn = blockIdx.x * 128;

    float acc[4][4][4];
#pragma unroll
    for (int i = 0; i < 4; i++)
#pragma unroll
        for (int j = 0; j < 4; j++)
#pragma unroll
            for (int k = 0; k < 4; k++) acc[i][j][k] = 0.f;

    const int nc = K >> 5;  // BK=32 chunks

    auto load_stage = [&](int c, int s) {
        const uint32_t base = sb0 + s * STAGE_B;
        const size_t k0 = (size_t)c << 5;
#pragma unroll
        for (int it = 0; it < 2; ++it) {
            int e = it * 256 + tid;
            int row = e >> 2, ch = e & 3;
            uint32_t d = base + row * ROW_B + ch * 16;
            size_t ga = ((size_t)(bm + row) * K + k0 + ch * 8) * 2;
            size_t gb = ((size_t)(bn + row) * K + k0 + ch * 8) * 2;
            CPA16(d,              (const char*)Ah + ga);
            CPA16(d + TILE_B,     (const char*)Al + ga);
            CPA16(d + 2 * TILE_B, (const char*)Bh + gb);
            CPA16(d + 3 * TILE_B, (const char*)Bl + gb);
        }
        CPA_COMMIT();
    };

    load_stage(0, 0);

    // per-warp ldmatrix base offsets (within a tile)
    const uint32_t a_off = (uint32_t)((wm * 64 + (lane & 15)) * ROW_B + (lane >> 4) * 16);
    const uint32_t b_off = (uint32_t)((wn * 32 + (lane & 7) + ((lane >> 4) << 3)) * ROW_B +
                                      ((lane >> 3) & 1) * 16);

    for (int c = 0; c < nc; ++c) {
        const int s = c & 1;
        if (c + 1 < nc) { load_stage(c + 1, (c + 1) & 1); CPA_WAIT1(); }
        else            { CPA_WAIT0(); }
        __syncthreads();

        const uint32_t base = sb0 + s * STAGE_B;
        const uint32_t ab = base + a_off;
        const uint32_t bb = base + 2 * TILE_B + b_off;
#pragma unroll
        for (int ks = 0; ks < 2; ++ks) {
            uint32_t a[4][4], bh[2][4], bl[2][4];
#pragma unroll
            for (int mf = 0; mf < 4; ++mf) ldsm4(a[mf], ab + mf * 16 * ROW_B + ks * 32);
#pragma unroll
            for (int nf = 0; nf < 2; ++nf) ldsm4(bh[nf], bb + nf * 16 * ROW_B + ks * 32);
#pragma unroll
            for (int nf = 0; nf < 2; ++nf) ldsm4(bl[nf], bb + TILE_B + nf * 16 * ROW_B + ks * 32);
            // pass 0: Ah * Bh
#pragma unroll
            for (int mf = 0; mf < 4; ++mf)
#pragma unroll
                for (int nf = 0; nf < 2; ++nf)
#pragma unroll
                    for (int sub = 0; sub < 2; ++sub)
                        mma16816(acc[mf][nf * 2 + sub], a[mf],
                                 bh[nf][sub * 2], bh[nf][sub * 2 + 1]);
            // pass 1: Ah * Bl
#pragma unroll
            for (int mf = 0; mf < 4; ++mf)
#pragma unroll
                for (int nf = 0; nf < 2; ++nf)
#pragma unroll
                    for (int sub = 0; sub < 2; ++sub)
                        mma16816(acc[mf][nf * 2 + sub], a[mf],
                                 bl[nf][sub * 2], bl[nf][sub * 2 + 1]);
            // reload a <- Al (reuse registers), pass 2: Al * Bh
#pragma unroll
            for (int mf = 0; mf < 4; ++mf) ldsm4(a[mf], ab + TILE_B + mf * 16 * ROW_B + ks * 32);
#pragma unroll
            for (int mf = 0; mf < 4; ++mf)
#pragma unroll
                for (int nf = 0; nf < 2; ++nf)
#pragma unroll
                    for (int sub = 0; sub < 2; ++sub)
                        mma16816(acc[mf][nf * 2 + sub], a[mf],
                                 bh[nf][sub * 2], bh[nf][sub * 2 + 1]);
        }
        __syncthreads();
    }

    // epilogue straight from fragments
#pragma unroll
    for (int mf = 0; mf < 4; ++mf) {
#pragma unroll
        for (int nf8 = 0; nf8 < 4; ++nf8) {
            int row = bm + wm * 64 + mf * 16 + (lane >> 2);
            int col = bn + wn * 32 + nf8 * 8 + (lane & 3) * 2;
            float b0 = bias[col], b1 = bias[col + 1];
#pragma unroll
            for (int half = 0; half < 2; ++half) {
                int r = row + half * 8;
                float v0 = acc[mf][nf8][half * 2 + 0] + b0;
                float v1 = acc[mf][nf8][half * 2 + 1] + b1;
                if (GELU) { v0 = v0 * normcdff(v0); v1 = v1 * normcdff(v1); }
                size_t o = (size_t)r * N + col;
                if (OUTMODE == 0) {
                    *(float2*)(Cf + o) = make_float2(v0, v1);
                } else {
                    __nv_bfloat16 h0, l0, h1, l1;
                    split2(v0, h0, l0); split2(v1, h1, l1);
                    *(__nv_bfloat162*)(Ch + o) = __nv_bfloat162(h0, h1);
                    *(__nv_bfloat162*)(Cl + o) = __nv_bfloat162(l0, l1);
                }
            }
        }
    }
}

// ---------------- weight fp32 -> (hi,lo) bf16, 3 segments in one launch ----
__global__ void cvtw3(const float* __restrict__ in_w, const float* __restrict__ fc1_w,
                      const float* __restrict__ fc2_w,
                      __nv_bfloat16* __restrict__ wh, __nv_bfloat16* __restrict__ wl) {
    int i = blockIdx.x * 256 + threadIdx.x;  // 0 .. 720895
    const float* src; int dst;
    if (i < 196608)      { src = in_w;  dst = OFF_INW  + i; }
    else if (i < 458752) { src = fc1_w - 196608; dst = OFF_FC1W + (i - 196608); }
    else                 { src = fc2_w - 458752; dst = OFF_FC2W + (i - 458752); }
    __nv_bfloat16 hh, ll;
    split2(src[i], hh, ll);
    wh[dst] = hh; wl[dst] = ll;
}

// ---------------- combined out∘proj weight: W = proj_w @ out_w ----------------
// attn@(out_w^T)@(proj_w^T) == attn@W^T ; b = proj_w@out_b + proj_b
__global__ void wcomb(const float* __restrict__ proj_w, const float* __restrict__ out_w,
                      const float* __restrict__ out_b, const float* __restrict__ proj_b,
                      __nv_bfloat16* __restrict__ wh, __nv_bfloat16* __restrict__ wl,
                      float* __restrict__ bcomb) {
    int i = blockIdx.x;       // output row
    int j = threadIdx.x;      // output col (coalesced over out_w)
    float s = 0.f;
    for (int k = 0; k < 256; ++k)
        s += proj_w[i * 256 + k] * out_w[k * 256 + j];
    __nv_bfloat16 hh, ll; split2(s, hh, ll);
    wh[OFF_CMBW + i * 256 + j] = hh;
    wl[OFF_CMBW + i * 256 + j] = ll;
    if (j == 0) {
        float b = proj_b[i];
        for (int k = 0; k < 256; ++k) b += proj_w[i * 256 + k] * out_b[k];
        bcomb[i] = b;
    }
}

// (b,h,w) -> token index T in shifted-window order
__device__ __forceinline__ int src_to_token(int b, int h, int w) {
    int hs = (h + 60) & 63, ws = (w + 60) & 63;
    return ((b * 8 + (hs >> 3)) * 8 + (ws >> 3)) * 64 + (hs & 7) * 8 + (ws & 7);
}

// ---------------- LN1 + shift + window partition -> bf16 hi/lo ----------------
#define LN_SMEM (256 * 65 * 4)
__global__ __launch_bounds__(256)
void ln1_part(const float* __restrict__ x,
              const float* __restrict__ g, const float* __restrict__ bb,
              __nv_bfloat16* __restrict__ oh, __nv_bfloat16* __restrict__ ol) {
    extern __shared__ float xs[];  // [256][65]
    int b = blockIdx.x >> 6, h = blockIdx.x & 63;
    int tid = threadIdx.x;
    const float* xp = x + (size_t)b * 1048576 + h * 64;
#pragma unroll
    for (int it = 0; it < 64; ++it) {
        int e = it * 256 + tid;
        int c = e >> 6, w = e & 63;
        xs[c * 65 + w] = xp[(size_t)c * 4096 + w];
    }
    __syncthreads();
    int warp = tid >> 5, lane = tid & 31;
#pragma unroll 1
    for (int t = 0; t < 8; ++t) {
        int w = t * 8 + warp;
        float v[8]; float s = 0.f;
#pragma unroll
        for (int k = 0; k < 8; k++) { v[k] = xs[(k * 32 + lane) * 65 + w]; s += v[k]; }
#pragma unroll
        for (int o = 16; o; o >>= 1) s += __shfl_xor_sync(0xffffffffu, s, o);
        float mu = s * 0.00390625f;
        float q = 0.f;
#pragma unroll
        for (int k = 0; k < 8; k++) { float d = v[k] - mu; q += d * d; }
#pragma unroll
        for (int o = 16; o; o >>= 1) q += __shfl_xor_sync(0xffffffffu, q, o);
        float rs = rsqrtf(q * 0.00390625f + 1e-6f);
        size_t tb = (size_t)src_to_token(b, h, w) * 256;
#pragma unroll
        for (int k = 0; k < 8; k++) {
            int c = k * 32 + lane;
            float val = (v[k] - mu) * rs * g[c] + bb[c];
            __nv_bfloat16 hh, ll; split2(val, hh, ll);
            oh[tb + c] = hh; ol[tb + c] = ll;
        }
    }
}

// ---------------- attention: one block per (window, head) ----------------
// QK^T: 4x4 register tile/thread; softmax: 4 lanes/row; SV: 2x4 tile w/ float4 V.
__global__ __launch_bounds__(256)
void attn_kernel(const float* __restrict__ qkv,
                 __nv_bfloat16* __restrict__ oh, __nv_bfloat16* __restrict__ ol) {
    __shared__ __align__(16) float Qs[64][33];
    __shared__ __align__(16) float Ks[64][33];
    __shared__ __align__(16) float Vs[64][36];
    __shared__ float S[64][65];
    __shared__ float rinv[64];
    int win = blockIdx.x, head = blockIdx.y;
    int tid = threadIdx.x;
    size_t base = (size_t)win * 64 * 768 + head * 32;

    // load q/k/v: 64 rows x 8 float4 each
#pragma unroll
    for (int e = tid; e < 512; e += 256) {
        int i = e >> 3, f4 = e & 7, d = f4 * 4;
        const float* rp = qkv + base + (size_t)i * 768;
        float4 q = *((const float4*)rp + f4);
        float4 k = *((const float4*)(rp + 256) + f4);
        float4 v = *((const float4*)(rp + 512) + f4);
        Qs[i][d] = q.x; Qs[i][d+1] = q.y; Qs[i][d+2] = q.z; Qs[i][d+3] = q.w;
        Ks[i][d] = k.x; Ks[i][d+1] = k.y; Ks[i][d+2] = k.z; Ks[i][d+3] = k.w;
        Vs[i][d] = v.x; Vs[i][d+1] = v.y; Vs[i][d+2] = v.z; Vs[i][d+3] = v.w;
    }
    __syncthreads();

    // QK^T, 4x4 per thread (16x16 thread grid)
    {
        int ti = (tid >> 4) * 4, tj = (tid & 15) * 4;
        float s[4][4];
#pragma unroll
        for (int r = 0; r < 4; ++r)
#pragma unroll
            for (int c2 = 0; c2 < 4; ++c2) s[r][c2] = 0.f;
#pragma unroll
        for (int d = 0; d < 32; ++d) {
            float qv[4], kv[4];
#pragma unroll
            for (int r = 0; r < 4; ++r) qv[r] = Qs[ti + r][d];
#pragma unroll
            for (int c2 = 0; c2 < 4; ++c2) kv[c2] = Ks[tj + c2][d];
#pragma unroll
            for (int r = 0; r < 4; ++r)
#pragma unroll
                for (int c2 = 0; c2 < 4; ++c2) s[r][c2] += qv[r] * kv[c2];
        }
        const float scale = 0.17677669529663687f;  // 1/sqrt(32)
#pragma unroll
        for (int r = 0; r < 4; ++r)
#pragma unroll
            for (int c2 = 0; c2 < 4; ++c2) S[ti + r][tj + c2] = s[r][c2] * scale;
    }
    __syncthreads();

    // softmax: 4 lanes per row, 16 cols each
    {
        int row = tid >> 2, j0 = (tid & 3) * 16;
        float m = -1e30f;
#pragma unroll
        for (int k = 0; k < 16; ++k) m = fmaxf(m, S[row][j0 + k]);
        m = fmaxf(m, __shfl_xor_sync(0xffffffffu, m, 1));
        m = fmaxf(m, __shfl_xor_sync(0xffffffffu, m, 2));
        float sum = 0.f;
#pragma unroll
        for (int k = 0; k < 16; ++k) {
            float e = __expf(S[row][j0 + k] - m);
            S[row][j0 + k] = e; sum += e;
        }
        sum += __shfl_xor_sync(0xffffffffu, sum, 1);
        sum += __shfl_xor_sync(0xffffffffu, sum, 2);
        if ((tid & 3) == 0) rinv[row] = 1.f / sum;
    }
    __syncthreads();

    // SV: 2 rows x 4 cols per thread
    {
        int r0 = (tid >> 3) * 2, dc = (tid & 7) * 4;
        float a0[4] = {0.f, 0.f, 0.f, 0.f}, a1[4] = {0.f, 0.f, 0.f, 0.f};
#pragma unroll
        for (int j = 0; j < 64; ++j) {
            float s0 = S[r0][j], s1 = S[r0 + 1][j];
            float4 v = *(const float4*)&Vs[j][dc];
            a0[0] += s0 * v.x; a0[1] += s0 * v.y; a0[2] += s0 * v.z; a0[3] += s0 * v.w;
            a1[0] += s1 * v.x; a1[1] += s1 * v.y; a1[2] += s1 * v.z; a1[3] += s1 * v.w;
        }
        float ri0 = rinv[r0], ri1 = rinv[r0 + 1];
        size_t o0 = (size_t)(win * 64 + r0) * 256 + head * 32 + dc;
#pragma unroll
        for (int c2 = 0; c2 < 4; ++c2) {
            __nv_bfloat16 hh, ll;
            split2(a0[c2] * ri0, hh, ll);
            oh[o0 + c2] = hh; ol[o0 + c2] = ll;
            split2(a1[c2] * ri1, hh, ll);
            oh[o0 + 256 + c2] = hh; ol[o0 + 256 + c2] = ll;
        }
    }
}

// ---------------- window reverse + residual + LN2 ----------------
__global__ __launch_bounds__(256)
void resid_ln2(const float* __restrict__ x, const float* __restrict__ a,
               const float* __restrict__ g, const float* __restrict__ bb,
               float* __restrict__ yout,
               __nv_bfloat16* __restrict__ zh, __nv_bfloat16* __restrict__ zl) {
    extern __shared__ float xs[];  // [256][65]
    int b = blockIdx.x >> 6, h = blockIdx.x & 63;
    int tid = threadIdx.x;
    const float* xp = x + (size_t)b * 1048576 + h * 64;
#pragma unroll
    for (int it = 0; it < 64; ++it) {
        int e = it * 256 + tid;
        int c = e >> 6, w = e & 63;
        xs[c * 65 + w] = xp[(size_t)c * 4096 + w];
    }
    __syncthreads();
    int warp = tid >> 5, lane = tid & 31;
#pragma unroll 1
    for (int t = 0; t < 8; ++t) {
        int w = t * 8 + warp;
        size_t tb = (size_t)src_to_token(b, h, w) * 256;
        float v[8]; float s = 0.f;
#pragma unroll
        for (int k = 0; k < 8; k++) {
            int c = k * 32 + lane;
            v[k] = xs[c * 65 + w] + a[tb + c];
            s += v[k];
        }
#pragma unroll
        for (int o = 16; o; o >>= 1) s += __shfl_xor_sync(0xffffffffu, s, o);
        float mu = s * 0.00390625f;
        float q = 0.f;
#pragma unroll
        for (int k = 0; k < 8; k++) { float d = v[k] - mu; q += d * d; }
#pragma unroll
        for (int o = 16; o; o >>= 1) q += __shfl_xor_sync(0xffffffffu, q, o);
        float rs = rsqrtf(q * 0.00390625f + 1e-6f);
#pragma unroll
        for (int k = 0; k < 8; k++) {
            int c = k * 32 + lane;
            yout[tb + c] = v[k];
            float val = (v[k] - mu) * rs * g[c] + bb[c];
            __nv_bfloat16 hh, ll; split2(val, hh, ll);
            zh[tb + c] = hh; zl[tb + c] = ll;
        }
    }
}

// ---------------- final: out[b,c,h,w] = y_tok + mlp_tok, smem transpose ----
#define FIN_SMEM (64 * 257 * 4)
__global__ __launch_bounds__(256)
void final_add(const float* __restrict__ y, const float* __restrict__ m,
               float* __restrict__ out) {
    extern __shared__ float ss[];  // [64 tokens][257]
    int b = blockIdx.x >> 6, h = blockIdx.x & 63;
    int tid = threadIdx.x;
    int warp = tid >> 5, lane = tid & 31;
#pragma unroll 1
    for (int t = 0; t < 8; ++t) {
        int w = t * 8 + warp;
        size_t tb = (size_t)src_to_token(b, h, w) * 256;
#pragma unroll
        for (int k = 0; k < 8; k++) {
            int c = k * 32 + lane;
            ss[w * 257 + c] = y[tb + c] + m[tb + c];
        }
    }
    __syncthreads();
    float* op = out + (size_t)b * 1048576 + h * 64;
#pragma unroll
    for (int it = 0; it < 64; ++it) {
        int e = it * 256 + tid;
        int c = e >> 6, w = e & 63;
        op[(size_t)c * 4096 + w] = ss[w * 257 + c];
    }
}

// ---------------- launch ----------------
extern "C" void kernel_launch(void* const* d_in, const int* in_sizes, int n_in,
                              void* d_out, int out_size) {
    const float* x      = (const float*)d_in[0];
    const float* n1g    = (const float*)d_in[1];
    const float* n1b    = (const float*)d_in[2];
    const float* in_w   = (const float*)d_in[3];
    const float* in_b   = (const float*)d_in[4];
    const float* out_w  = (const float*)d_in[5];
    const float* out_b  = (const float*)d_in[6];
    const float* proj_w = (const float*)d_in[7];
    const float* proj_b = (const float*)d_in[8];
    const float* n2g    = (const float*)d_in[9];
    const float* n2b    = (const float*)d_in[10];
    const float* fc1_w  = (const float*)d_in[11];
    const float* fc1_b  = (const float*)d_in[12];
    const float* fc2_w  = (const float*)d_in[13];
    const float* fc2_b  = (const float*)d_in[14];
    float* out = (float*)d_out;

    __nv_bfloat16 *xnh, *xnl, *ath, *atl, *zh, *zl, *h1h, *h1l, *wh, *wl;
    float *qkv, *attn2, *yb, *mlp, *bcomb;
    cudaGetSymbolAddress((void**)&xnh,   g_xn_h);
    cudaGetSymbolAddress((void**)&xnl,   g_xn_l);
    cudaGetSymbolAddress((void**)&qkv,   g_qkv);
    cudaGetSymbolAddress((void**)&ath,   g_at_h);
    cudaGetSymbolAddress((void**)&atl,   g_at_l);
    cudaGetSymbolAddress((void**)&attn2, g_attn2);
    cudaGetSymbolAddress((void**)&yb,    g_y);
    cudaGetSymbolAddress((void**)&zh,    g_z_h);
    cudaGetSymbolAddress((void**)&zl,    g_z_l);
    cudaGetSymbolAddress((void**)&h1h,   g_h1_h);
    cudaGetSymbolAddress((void**)&h1l,   g_h1_l);
    cudaGetSymbolAddress((void**)&mlp,   g_mlp);
    cudaGetSymbolAddress((void**)&wh,    g_w_h);
    cudaGetSymbolAddress((void**)&wl,    g_w_l);
    cudaGetSymbolAddress((void**)&bcomb, g_bcomb);

    cudaFuncSetAttribute(mma_gemm<0, false>, cudaFuncAttributeMaxDynamicSharedMemorySize, GEMM_SMEM);
    cudaFuncSetAttribute(mma_gemm<1, false>, cudaFuncAttributeMaxDynamicSharedMemorySize, GEMM_SMEM);
    cudaFuncSetAttribute(mma_gemm<1, true >, cudaFuncAttributeMaxDynamicSharedMemorySize, GEMM_SMEM);
    cudaFuncSetAttribute(ln1_part,  cudaFuncAttributeMaxDynamicSharedMemorySize, LN_SMEM);
    cudaFuncSetAttribute(resid_ln2, cudaFuncAttributeMaxDynamicSharedMemorySize, LN_SMEM);
    cudaFuncSetAttribute(final_add, cudaFuncAttributeMaxDynamicSharedMemorySize, FIN_SMEM);

    // prep: weight split (1 launch) + combined out/proj weight
    cvtw3<<<2816, 256>>>(in_w, fc1_w, fc2_w, wh, wl);
    wcomb<<<256, 256>>>(proj_w, out_w, out_b, proj_b, wh, wl, bcomb);

    ln1_part<<<1024, 256, LN_SMEM>>>(x, n1g, n1b, xnh, xnl);

    // qkv: [65536,768] = xn @ in_w^T
    mma_gemm<0, false><<<dim3(6, 512), 256, GEMM_SMEM>>>(
        xnh, xnl, wh + OFF_INW, wl + OFF_INW, in_b, qkv, nullptr, nullptr, 768, 256);

    attn_kernel<<<dim3(1024, 8), 256>>>(qkv, ath, atl);

    // combined out_w∘proj_w: [65536,256]
    mma_gemm<0, false><<<dim3(2, 512), 256, GEMM_SMEM>>>(
        ath, atl, wh + OFF_CMBW, wl + OFF_CMBW, bcomb, attn2, nullptr, nullptr, 256, 256);

    resid_ln2<<<1024, 256, LN_SMEM>>>(x, attn2, n2g, n2b, yb, zh, zl);

    // fc1 + gelu: [65536,1024]
    mma_gemm<1, true><<<dim3(8, 512), 256, GEMM_SMEM>>>(
        zh, zl, wh + OFF_FC1W, wl + OFF_FC1W, fc1_b, nullptr, h1h, h1l, 1024, 256);

    // fc2: [65536,256], K=1024
    mma_gemm<0, false><<<dim3(2, 512), 256, GEMM_SMEM>>>(
        h1h, h1l, wh + OFF_FC2W, wl + OFF_FC2W, fc2_b, mlp, nullptr, nullptr, 256, 1024);

    final_add<<<1024, 256, FIN_SMEM>>>(yb, mlp, out);
}